// round 15
// baseline (speedup 1.0000x reference)
#include <cuda_runtime.h>

// Problem constants
#define B_    4
#define C_    256
#define H_    64
#define W_    64
#define HW_   4096
#define NUM_  9
#define NC_   27   // candidates per pixel after propagate
#define K_    9    // top-k kept

// Scratch (no allocations allowed — use __device__ globals)
__device__ float g_leftT [(size_t)B_ * HW_ * C_];   // [b][pixel][c]
__device__ float g_rightT[(size_t)B_ * HW_ * C_];   // [b*HW+p][c]
__device__ int   g_inds1 [B_ * NUM_ * HW_];         // pass-1 top-9 inds, [b][k][hw]

// ---------------------------------------------------------------------------
// exp(d) for d <= 0: IEEE-754 float32 bit pattern of the RN result.
// Subnormal results produced exactly; caller flushes them (XLA-GPU FTZ).
// Immune to -ftz / fast-math (integer bit assembly, normal-range float ops).
// ---------------------------------------------------------------------------
__device__ __forceinline__ unsigned exp_f32_bits(float d)
{
    if (d < -106.0f) return 0u;
    float t  = d * 1.4426950408889634f;            // log2(e)
    float fi = floorf(t);
    float f  = t - fi;                             // [0, 1)
    int   i  = (int)fi;
    float p2 = fmaf(f, 1.0178086e-07f, 1.3215487e-06f);
    p2 = fmaf(f, p2, 1.5252734e-05f);
    p2 = fmaf(f, p2, 1.5403530e-04f);
    p2 = fmaf(f, p2, 1.3333558e-03f);
    p2 = fmaf(f, p2, 9.6181291e-03f);
    p2 = fmaf(f, p2, 5.5504109e-02f);
    p2 = fmaf(f, p2, 2.4022651e-01f);
    p2 = fmaf(f, p2, 6.9314718e-01f);
    p2 = fmaf(f, p2, 1.0f);
    if (i >= -126) {
        unsigned S = __float2uint_rn(p2 * 8388608.0f);
        if (S >= (1u << 24)) { S >>= 1; i += 1; }
        return (((unsigned)(i + 127)) << 23) + (S - (1u << 23));
    } else {
        float v = ldexpf(p2, i + 149);
        return __float2uint_rn(v);                 // subnormal bits
    }
}

// ---------------------------------------------------------------------------
// Fused vectorized transpose, 32 x 256 tiles (two 32x128 halves -> 8
// independent LDG.128 in flight per thread). z = 0..3 left, 4..7 right.
// XOR-swizzled float4 smem tiles (conflict-free both phases):
//   element (r, c) lives at tile[r*32 + ((c>>2) ^ (r>>2))], component c&3.
// ---------------------------------------------------------------------------
__global__ void __launch_bounds__(256) transpose_kernel(
    const float* __restrict__ left, const float* __restrict__ right)
{
    __shared__ float4 tA[32 * 32], tB[32 * 32];       // 32 KB
    const float* tAf = reinterpret_cast<const float*>(tA);
    const float* tBf = reinterpret_cast<const float*>(tB);
    int tx = threadIdx.x, ty = threadIdx.y;           // (32, 8)
    int bx = blockIdx.x, by = blockIdx.y, bz = blockIdx.z;

    bool is_right = bz >= 4;
    int  bb       = is_right ? bz - 4 : bz;
    const float* ip = is_right ? (right + (long)bb * HW_)
                               : (left  + (long)bb * C_ * HW_);
    long rstride   = is_right ? (long)B_ * HW_ : (long)HW_;
    float* op      = (is_right ? g_rightT : g_leftT) + (long)bb * HW_ * C_;

    // load: 32 rows (C-dim) x 256 cols (HW-dim); 2 float4 per thread per iter
#pragma unroll
    for (int i = 0; i < 4; i++) {
        int rr  = ty + i * 8;
        const float* rowp = ip + (long)(by * 32 + rr) * rstride + bx * 256;
        float4 vA = *reinterpret_cast<const float4*>(rowp + tx * 4);
        float4 vB = *reinterpret_cast<const float4*>(rowp + 128 + tx * 4);
        tA[rr * 32 + (tx ^ (rr >> 2))] = vA;
        tB[rr * 32 + (tx ^ (rr >> 2))] = vB;
    }
    __syncthreads();

    // store: 2048 output float4s (256 out-rows x 8 float4s); 8 per thread
    int tid = ty * 32 + tx;
#pragma unroll
    for (int it = 0; it < 8; it++) {
        int j    = it * 256 + tid;
        int half = j >> 10;                // 0: cols 0..127, 1: 128..255
        int jj   = j & 1023;
        int cc   = jj >> 3;                // out row within half (HW-dim)
        int rrb  = (jj & 7) * 4;           // out col base (C-dim)
        int q    = cc >> 2;
        const float* tf = half ? tBf : tAf;
        float4 v;
        v.x = tf[(rrb + 0) * 128 + ((q ^ ((rrb + 0) >> 2)) << 2) + (cc & 3)];
        v.y = tf[(rrb + 1) * 128 + ((q ^ ((rrb + 1) >> 2)) << 2) + (cc & 3)];
        v.z = tf[(rrb + 2) * 128 + ((q ^ ((rrb + 2) >> 2)) << 2) + (cc & 3)];
        v.w = tf[(rrb + 3) * 128 + ((q ^ ((rrb + 3) >> 2)) << 2) + (cc & 3)];
        *reinterpret_cast<float4*>(
            op + (long)(bx * 256 + half * 128 + cc) * C_ + by * 32 + rrb) = v;
    }
}

// ---------------------------------------------------------------------------
// Fused evaluate: TWO warps per pixel (channel halves), 4 pixels per block
// (consecutive x, same row/batch). Scattered small IO (pass-2 candidate
// indices, all outputs) is staged through smem so每 global access is a
// coalesced 16B+ chunk. Gather/reduce/softmax/rank identical to R12.
// PASS==1: horizontal propagate from raw float offsets, write top-9 inds.
// PASS==2: vertical propagate from g_inds1, write ox / oy / corr to output.
// ---------------------------------------------------------------------------
template <int PASS>
__global__ void __launch_bounds__(256, 5)
eval_kernel(const float* __restrict__ offx,
            const float* __restrict__ offy,
            float* __restrict__ out)
{
    const unsigned FULL = 0xffffffffu;
    int t    = threadIdx.x;
    int warp = t >> 5;
    int lane = t & 31;
    int pixw = warp >> 1;               // pixel-in-block 0..3
    int h    = warp & 1;                // channel half
    int gw0  = blockIdx.x * 4;          // first pixel of block
    int b    = gw0 >> 12;
    int hw0  = gw0 & (HW_ - 1);
    int y    = hw0 >> 6;
    int x0   = hw0 & 63;                // block covers x0..x0+3
    int hw   = hw0 + pixw;
    int x    = x0 + pixw;

    __shared__ float s_half[4][2][32];
    __shared__ int   s_ind[NC_][4];                 // PASS2 inputs
    __shared__ float s_offx[NUM_][6], s_offy[NUM_][6];  // PASS1 inputs
    __shared__ int   s_i1[NUM_][4];                 // PASS1 outputs
    __shared__ float s_out[3][NUM_][4];             // PASS2 outputs

    // --- cooperative, coalesced input staging ---
    if (PASS == 1) {
        if (t < 54) {                   // 9 rows x 6 columns (x0-1 .. x0+4)
            int j = t / 6, xi = t % 6;
            int gx = x0 - 1 + xi;
            if (gx >= 0 && gx < W_) {
                int o = (b * NUM_ + j) * HW_ + y * W_ + gx;
                s_offx[j][xi] = offx[o];
                s_offy[j][xi] = offy[o];
            }
        }
    } else {
        if (t < 108) {                  // 27 (cand) rows x 4 pixel columns
            int r = t >> 2, xi = t & 3;
            int g = (r >= 18) ? 2 : ((r >= 9) ? 1 : 0);
            int j = r - g * 9;
            int sy = y + g - 1;
            if (sy >= 0 && sy < H_)
                s_ind[r][xi] = g_inds1[(b * NUM_ + j) * HW_ + sy * W_ + x0 + xi];
        }
    }
    __syncthreads();

    // --- candidate indices: lane n < 27 owns candidate n (both warps) ---
    // n = g*9 + j : g=0 left/up neighbor, g=1 self, g=2 right/down neighbor.
    // Out-of-image neighbor => padded offset 0 => candidate = self pixel.
    int cand = hw;
    if (lane < NC_) {
        int g = (lane >= 18) ? 2 : ((lane >= 9) ? 1 : 0);
        int j = lane - g * 9;
        if (PASS == 1) {
            int sx = x + g - 1;
            if (sx >= 0 && sx < W_) {
                float ox = s_offx[j][pixw + g];
                float oy = s_offy[j][pixw + g];
                float px = fminf(fmaxf((float)x + ox, 0.f), (float)(W_ - 1));
                float py = fminf(fmaxf((float)y + oy, 0.f), (float)(H_ - 1));
                cand = (int)(py * (float)W_ + px);
            }
        } else {
            int sy = y + g - 1;
            if (sy >= 0 && sy < H_) {
                int ip = s_ind[lane][pixw];
                int ix = ip & 63;
                int iy = ip >> 6;
                int py = min(max(iy + (y - sy), 0), H_ - 1);
                cand = py * W_ + ix;
            }
        }
    }

    // --- left feature vector: 4 channels per lane (this warp's half) ---
    const float4 L = *reinterpret_cast<const float4*>(
        g_leftT + (size_t)(b * HW_ + hw) * C_ + h * 128 + lane * 4);

    // --- 27 gathered per-lane partial dots (4 channels each) ---
    const float* rbase = g_rightT + (size_t)b * HW_ * C_ + h * 128 + lane * 4;
    float acc[NC_];
#pragma unroll
    for (int n = 0; n < NC_; n++) {
        int ind = __shfl_sync(FULL, cand, n);
        float4 r = *reinterpret_cast<const float4*>(rbase + (size_t)ind * C_);
        float s = L.x * r.x;
        s = fmaf(L.y, r.y, s);
        s = fmaf(L.z, r.z, s);
        s = fmaf(L.w, r.w, s);
        acc[n] = s;
    }

    // --- recursive vector-halving reduction: 31 shuffles + 31 adds.
    //     Afterwards lane n holds this half's 128-channel dot of cand n. ---
#pragma unroll
    for (int m = 16; m >= 1; m >>= 1) {
        bool hi = (lane & m) != 0;
#pragma unroll
        for (int i = 0; i < m; i++) {
            float hiv  = (i + m < NC_) ? acc[i + m] : 0.f;
            float send = hi ? acc[i] : hiv;
            float recv = __shfl_xor_sync(FULL, send, m);
            float keep = hi ? hiv : acc[i];
            acc[i] = keep + recv;
        }
    }

    // --- combine halves through smem; only h=0 warps run the tail ---
    s_half[pixw][h][lane] = acc[0];
    __syncthreads();

    if (h == 0) {
        float dot  = s_half[pixw][0][lane] + s_half[pixw][1][lane];
        float cost = (lane < NC_) ? __fdiv_rn(dot, 0.01f) : -3.402823466e38f;

        // --- warp max (bitwise-identical on all lanes) ---
        float mx = cost;
#pragma unroll
        for (int off = 16; off > 0; off >>= 1)
            mx = fmaxf(mx, __shfl_xor_sync(FULL, mx, off));

        // --- one exp per lane, flush subnormal (XLA-GPU FTZ emulation) ---
        unsigned e = (lane < NC_) ? exp_f32_bits(cost - mx) : 0u;
        if (e < 0x00800000u) e = 0u;
        float ef = __uint_as_float(e);

        // --- warp sum (butterfly: identical result on all lanes) ---
        float ps = ef;
#pragma unroll
        for (int off = 16; off > 0; off >>= 1)
            ps += __shfl_xor_sync(FULL, ps, off);

        unsigned p = __float_as_uint(__fdiv_rn(ef, ps));
        if (p < 0x00800000u) p = 0u;               // flush subnormal prob

        // --- rank of own candidate among 27 (descending prob, lowest slot
        //     wins ties == jax.lax.top_k stable order). Ranks form a
        //     permutation, so each staging slot is written exactly once. ---
        int rank = 0;
#pragma unroll
        for (int m2 = 0; m2 < NC_; m2++) {
            unsigned pm = __shfl_sync(FULL, p, m2);
            rank += (int)((pm > p) | ((pm == p) & (m2 < lane)));
        }

        if (lane < NC_ && rank < K_) {
            if (PASS == 1) {
                s_i1[rank][pixw] = cand;
            } else {
                s_out[0][rank][pixw] = (float)((cand & 63) - x);   // ox
                s_out[1][rank][pixw] = (float)((cand >> 6) - y);   // oy
                s_out[2][rank][pixw] = __uint_as_float(p);         // corr
            }
        }
    }
    __syncthreads();

    // --- cooperative, coalesced output write (16B chunks) ---
    if (PASS == 1) {
        if (t < 36) {
            int k = t >> 2, xi = t & 3;
            g_inds1[(b * NUM_ + k) * HW_ + hw0 + xi] = s_i1[k][xi];
        }
    } else {
        if (t < 108) {
            int field = t / 36;
            int rem   = t - field * 36;
            int k  = rem >> 2, xi = rem & 3;
            out[field * (B_ * NUM_ * HW_) + (b * NUM_ + k) * HW_ + hw0 + xi] =
                s_out[field][k][xi];
        }
    }
}

// ---------------------------------------------------------------------------
extern "C" void kernel_launch(void* const* d_in, const int* in_sizes, int n_in,
                              void* d_out, int out_size)
{
    const float* left  = (const float*)d_in[0];  // (B, C, HW)
    const float* right = (const float*)d_in[1];  // (C, B*HW)
    const float* offx  = (const float*)d_in[2];  // (B, 9, H, W)
    const float* offy  = (const float*)d_in[3];  // (B, 9, H, W)
    float* out = (float*)d_out;                  // ox | oy | corr concatenated

    dim3 tb(32, 8);
    dim3 tg(HW_ / 256, C_ / 32, 2 * B_);         // z: 0..3 left, 4..7 right
    transpose_kernel<<<tg, tb>>>(left, right);

    int nblocks = (B_ * HW_) / 4;   // 4 pixels x 2 warps per 256-thread block
    eval_kernel<1><<<nblocks, 256>>>(offx, offy, nullptr);
    eval_kernel<2><<<nblocks, 256>>>(nullptr, nullptr, out);
}

// round 16
// speedup vs baseline: 1.0360x; 1.0360x over previous
#include <cuda_runtime.h>

// Problem constants
#define B_    4
#define C_    256
#define H_    64
#define W_    64
#define HW_   4096
#define NUM_  9
#define NC_   27   // candidates per pixel after propagate
#define K_    9    // top-k kept

// Scratch (no allocations allowed — use __device__ globals)
__device__ float g_leftT [(size_t)B_ * HW_ * C_];   // [b][pixel][c]
__device__ float g_rightT[(size_t)B_ * HW_ * C_];   // [b*HW+p][c]
__device__ int   g_inds1 [B_ * NUM_ * HW_];         // pass-1 top-9 inds, [b][k][hw]

// ---------------------------------------------------------------------------
// exp(d) for d <= 0: IEEE-754 float32 bit pattern of the RN result.
// Subnormal results produced exactly; caller flushes them (XLA-GPU FTZ).
// Immune to -ftz / fast-math (integer bit assembly, normal-range float ops).
// ---------------------------------------------------------------------------
__device__ __forceinline__ unsigned exp_f32_bits(float d)
{
    if (d < -106.0f) return 0u;
    float t  = d * 1.4426950408889634f;            // log2(e)
    float fi = floorf(t);
    float f  = t - fi;                             // [0, 1)
    int   i  = (int)fi;
    float p2 = fmaf(f, 1.0178086e-07f, 1.3215487e-06f);
    p2 = fmaf(f, p2, 1.5252734e-05f);
    p2 = fmaf(f, p2, 1.5403530e-04f);
    p2 = fmaf(f, p2, 1.3333558e-03f);
    p2 = fmaf(f, p2, 9.6181291e-03f);
    p2 = fmaf(f, p2, 5.5504109e-02f);
    p2 = fmaf(f, p2, 2.4022651e-01f);
    p2 = fmaf(f, p2, 6.9314718e-01f);
    p2 = fmaf(f, p2, 1.0f);
    if (i >= -126) {
        unsigned S = __float2uint_rn(p2 * 8388608.0f);
        if (S >= (1u << 24)) { S >>= 1; i += 1; }
        return (((unsigned)(i + 127)) << 23) + (S - (1u << 23));
    } else {
        float v = ldexpf(p2, i + 149);
        return __float2uint_rn(v);                 // subnormal bits
    }
}

// ---------------------------------------------------------------------------
// Fused vectorized transpose (R14 form): 32 x 128 tiles, float4 global loads
// and stores, XOR-swizzled float4 smem tile (conflict-free both phases).
//   element (r, c) lives at tile4[r*32 + ((c>>2) ^ (r>>2))], component c&3.
// z = 0..3 -> left batch z, z = 4..7 -> right batch z-4.
// ---------------------------------------------------------------------------
__global__ void __launch_bounds__(256) transpose_kernel(
    const float* __restrict__ left, const float* __restrict__ right)
{
    __shared__ float4 tile4[32 * 32];                 // 16 KB
    const float* tilef = reinterpret_cast<const float*>(tile4);
    int tx = threadIdx.x, ty = threadIdx.y;           // (32, 8)
    int bx = blockIdx.x, by = blockIdx.y, bz = blockIdx.z;

    bool is_right = bz >= 4;
    int  bb       = is_right ? bz - 4 : bz;
    const float* ip = is_right ? (right + (long)bb * HW_)
                               : (left  + (long)bb * C_ * HW_);
    long rstride   = is_right ? (long)B_ * HW_ : (long)HW_;
    float* op      = (is_right ? g_rightT : g_leftT) + (long)bb * HW_ * C_;

#pragma unroll
    for (int i = 0; i < 4; i++) {
        int rr  = ty + i * 8;
        int r_g = by * 32 + rr;
        float4 v = *reinterpret_cast<const float4*>(
            ip + (long)r_g * rstride + bx * 128 + tx * 4);
        tile4[rr * 32 + (tx ^ (rr >> 2))] = v;
    }
    __syncthreads();

    int tid = ty * 32 + tx;
#pragma unroll
    for (int it = 0; it < 4; it++) {
        int j    = it * 256 + tid;
        int cc   = j >> 3;
        int rrb  = (j & 7) * 4;
        int q    = cc >> 2;
        float4 v;
        v.x = tilef[(rrb + 0) * 128 + ((q ^ ((rrb + 0) >> 2)) << 2) + (cc & 3)];
        v.y = tilef[(rrb + 1) * 128 + ((q ^ ((rrb + 1) >> 2)) << 2) + (cc & 3)];
        v.z = tilef[(rrb + 2) * 128 + ((q ^ ((rrb + 2) >> 2)) << 2) + (cc & 3)];
        v.w = tilef[(rrb + 3) * 128 + ((q ^ ((rrb + 3) >> 2)) << 2) + (cc & 3)];
        *reinterpret_cast<float4*>(
            op + (long)(bx * 128 + cc) * C_ + by * 32 + rrb) = v;
    }
}

// 5-level vector-halving warp reduction over a 16-slot candidate vector.
// Afterwards lane n holds the full cross-lane sum of slot n (n < 16).
__device__ __forceinline__ float halve_reduce16(float (&acc)[16], int lane)
{
    const unsigned FULL = 0xffffffffu;
#pragma unroll
    for (int m = 16; m >= 1; m >>= 1) {
        bool hi = (lane & m) != 0;
#pragma unroll
        for (int i = 0; i < m; i++) {
            float hiv  = (i + m < 16) ? acc[i + m] : 0.f;
            float send = hi ? acc[i] : hiv;
            float recv = __shfl_xor_sync(FULL, send, m);
            float keep = hi ? hiv : acc[i];
            acc[i] = keep + recv;
        }
    }
    return acc[0];
}

// ---------------------------------------------------------------------------
// Fused evaluate: TWO warps per pixel (channel halves), candidates processed
// in two phases of 16 + 11 to cap live accumulators at 16 (regs -> higher
// occupancy for latency hiding). Halves combine via a small smem exchange.
// PASS==1: horizontal propagate from raw float offsets, write top-9 inds.
// PASS==2: vertical propagate from g_inds1, write ox / oy / corr to output.
// ---------------------------------------------------------------------------
template <int PASS>
__global__ void __launch_bounds__(256, 6)
eval_kernel(const float* __restrict__ offx,
            const float* __restrict__ offy,
            float* __restrict__ out)
{
    const unsigned FULL = 0xffffffffu;
    int t    = threadIdx.x;
    int warp = t >> 5;
    int lane = t & 31;
    int pixw = warp >> 1;               // pixel-in-block 0..3
    int h    = warp & 1;                // channel half
    int gw   = blockIdx.x * 4 + pixw;   // global pixel
    int b  = gw >> 12;
    int hw = gw & (HW_ - 1);
    int y = hw >> 6, x = hw & 63;

    __shared__ float s_half[4][2][32];

    // --- candidate indices: lane n < 27 owns candidate n (both warps) ---
    // n = g*9 + j : g=0 left/up neighbor, g=1 self, g=2 right/down neighbor.
    // Out-of-image neighbor => padded offset 0 => candidate = self pixel.
    int cand = hw;
    if (lane < NC_) {
        int g = (lane >= 18) ? 2 : ((lane >= 9) ? 1 : 0);
        int j = lane - g * 9;
        if (PASS == 1) {
            int sx = x + g - 1;
            if (sx >= 0 && sx < W_) {
                int o = ((b * NUM_ + j) * H_ + y) * W_ + sx;
                float ox = offx[o];
                float oy = offy[o];
                float px = fminf(fmaxf((float)x + ox, 0.f), (float)(W_ - 1));
                float py = fminf(fmaxf((float)y + oy, 0.f), (float)(H_ - 1));
                cand = (int)(py * (float)W_ + px);
            }
        } else {
            int sy = y + g - 1;
            if (sy >= 0 && sy < H_) {
                int ip = g_inds1[(b * NUM_ + j) * HW_ + sy * W_ + x];
                int ix = ip & 63;
                int iy = ip >> 6;
                int py = min(max(iy + (y - sy), 0), H_ - 1);
                cand = py * W_ + ix;
            }
        }
    }

    // --- left feature vector: 4 channels per lane (this warp's half) ---
    const float4 L = *reinterpret_cast<const float4*>(
        g_leftT + (size_t)(b * HW_ + hw) * C_ + h * 128 + lane * 4);

    const float* rbase = g_rightT + (size_t)b * HW_ * C_ + h * 128 + lane * 4;

    // ===== phase A: candidates 0..15 =====
    float dotA;
    {
        float acc[16];
#pragma unroll
        for (int n = 0; n < 16; n++) {
            int ind = __shfl_sync(FULL, cand, n);
            float4 r = *reinterpret_cast<const float4*>(rbase + (size_t)ind * C_);
            float s = L.x * r.x;
            s = fmaf(L.y, r.y, s);
            s = fmaf(L.z, r.z, s);
            s = fmaf(L.w, r.w, s);
            acc[n] = s;
        }
        dotA = halve_reduce16(acc, lane);          // lane n: candidate n
    }

    // ===== phase B: candidates 16..26 (slots 0..10; rest literal zero) =====
    float dotB;
    {
        float acc[16];
#pragma unroll
        for (int n = 0; n < 11; n++) {
            int ind = __shfl_sync(FULL, cand, 16 + n);
            float4 r = *reinterpret_cast<const float4*>(rbase + (size_t)ind * C_);
            float s = L.x * r.x;
            s = fmaf(L.y, r.y, s);
            s = fmaf(L.z, r.z, s);
            s = fmaf(L.w, r.w, s);
            acc[n] = s;
        }
#pragma unroll
        for (int n = 11; n < 16; n++) acc[n] = 0.f;
        dotB = halve_reduce16(acc, lane);          // lane n: candidate 16+n
    }

    // own-candidate half-dot: lanes 0..15 from A, lanes 16..26 from B(lane-16)
    float dotBsh = __shfl_sync(FULL, dotB, (lane - 16) & 31);
    float hdot   = (lane < 16) ? dotA : dotBsh;

    // --- combine halves through smem; only h=0 warps run the tail ---
    s_half[pixw][h][lane] = hdot;
    __syncthreads();

    if (h == 0) {
        float dot  = s_half[pixw][0][lane] + s_half[pixw][1][lane];
        float cost = (lane < NC_) ? __fdiv_rn(dot, 0.01f) : -3.402823466e38f;

        // --- warp max (bitwise-identical on all lanes) ---
        float mx = cost;
#pragma unroll
        for (int off = 16; off > 0; off >>= 1)
            mx = fmaxf(mx, __shfl_xor_sync(FULL, mx, off));

        // --- one exp per lane, flush subnormal (XLA-GPU FTZ emulation) ---
        unsigned e = (lane < NC_) ? exp_f32_bits(cost - mx) : 0u;
        if (e < 0x00800000u) e = 0u;
        float ef = __uint_as_float(e);

        // --- warp sum (butterfly: identical result on all lanes) ---
        float ps = ef;
#pragma unroll
        for (int off = 16; off > 0; off >>= 1)
            ps += __shfl_xor_sync(FULL, ps, off);

        unsigned p = __float_as_uint(__fdiv_rn(ef, ps));
        if (p < 0x00800000u) p = 0u;               // flush subnormal prob

        // --- rank of own candidate among 27 (descending prob, lowest slot
        //     wins ties == jax.lax.top_k stable order). rank<9 lanes write ---
        int rank = 0;
#pragma unroll
        for (int m2 = 0; m2 < NC_; m2++) {
            unsigned pm = __shfl_sync(FULL, p, m2);
            rank += (int)((pm > p) | ((pm == p) & (m2 < lane)));
        }

        if (lane < NC_ && rank < K_) {
            int o = (b * NUM_ + rank) * HW_ + hw;
            if (PASS == 1) {
                g_inds1[o] = cand;
            } else {
                out[o]                       = (float)((cand & 63) - x);  // ox
                out[B_ * NUM_ * HW_ + o]     = (float)((cand >> 6) - y);  // oy
                out[2 * B_ * NUM_ * HW_ + o] = __uint_as_float(p);        // corr
            }
        }
    }
}

// ---------------------------------------------------------------------------
extern "C" void kernel_launch(void* const* d_in, const int* in_sizes, int n_in,
                              void* d_out, int out_size)
{
    const float* left  = (const float*)d_in[0];  // (B, C, HW)
    const float* right = (const float*)d_in[1];  // (C, B*HW)
    const float* offx  = (const float*)d_in[2];  // (B, 9, H, W)
    const float* offy  = (const float*)d_in[3];  // (B, 9, H, W)
    float* out = (float*)d_out;                  // ox | oy | corr concatenated

    dim3 tb(32, 8);
    dim3 tg(HW_ / 128, C_ / 32, 2 * B_);         // z: 0..3 left, 4..7 right
    transpose_kernel<<<tg, tb>>>(left, right);

    int nblocks = (B_ * HW_) / 4;   // 4 pixels x 2 warps per 256-thread block
    eval_kernel<1><<<nblocks, 256>>>(offx, offy, nullptr);
    eval_kernel<2><<<nblocks, 256>>>(nullptr, nullptr, out);
}